// round 3
// baseline (speedup 1.0000x reference)
#include <cuda_runtime.h>
#include <cuda_bf16.h>

// MedianPool2d 3x3, zero padding, on x: [16, 3, 512, 512] fp32.
// Exact median-of-9 via separable column-sort decomposition:
//   per column sort 3 vertically -> (lo, mid, hi)
//   median9(x-1..x+1) = med3( max3(lo), med3(mid), min3(hi) )
// Each thread produces an 8-pixel horizontal run in one row.

#define MP_W 512
#define MP_H 512
#define MP_BC 48          // 16 * 3
#define MP_TX 8           // pixels per thread
#define MP_SEGS 64        // MP_W / MP_TX

__device__ __forceinline__ float med3f(float a, float b, float c) {
    // median of 3 in 4 min/max ops
    return fmaxf(fminf(a, b), fminf(fmaxf(a, b), c));
}

__global__ __launch_bounds__(256, 8)
void median3x3_kernel(const float* __restrict__ in, float* __restrict__ out) {
    const int gid = blockIdx.x * 256 + threadIdx.x;
    const int seg = gid & (MP_SEGS - 1);          // bits [0,6)
    const int y   = (gid >> 6) & (MP_H - 1);      // bits [6,15)
    const int bc  = gid >> 15;                    // bits [15,...)
    const int xs  = seg * MP_TX;

    const float* base = in + (size_t)bc * (MP_H * MP_W);

    float r0[MP_TX + 2];  // row y-1
    float r1[MP_TX + 2];  // row y
    float r2[MP_TX + 2];  // row y+1

    // ---- load row y (always valid) ----
    {
        const float* row = base + y * MP_W;
        float4 a = *(const float4*)(row + xs);
        float4 b = *(const float4*)(row + xs + 4);
        r1[1] = a.x; r1[2] = a.y; r1[3] = a.z; r1[4] = a.w;
        r1[5] = b.x; r1[6] = b.y; r1[7] = b.z; r1[8] = b.w;
        r1[0] = (xs > 0)            ? row[xs - 1]     : 0.0f;
        r1[9] = (xs + MP_TX < MP_W) ? row[xs + MP_TX] : 0.0f;
    }
    // ---- load row y-1 (zero pad at top) ----
    if (y > 0) {
        const float* row = base + (y - 1) * MP_W;
        float4 a = *(const float4*)(row + xs);
        float4 b = *(const float4*)(row + xs + 4);
        r0[1] = a.x; r0[2] = a.y; r0[3] = a.z; r0[4] = a.w;
        r0[5] = b.x; r0[6] = b.y; r0[7] = b.z; r0[8] = b.w;
        r0[0] = (xs > 0)            ? row[xs - 1]     : 0.0f;
        r0[9] = (xs + MP_TX < MP_W) ? row[xs + MP_TX] : 0.0f;
    } else {
        #pragma unroll
        for (int i = 0; i < MP_TX + 2; i++) r0[i] = 0.0f;
    }
    // ---- load row y+1 (zero pad at bottom) ----
    if (y < MP_H - 1) {
        const float* row = base + (y + 1) * MP_W;
        float4 a = *(const float4*)(row + xs);
        float4 b = *(const float4*)(row + xs + 4);
        r2[1] = a.x; r2[2] = a.y; r2[3] = a.z; r2[4] = a.w;
        r2[5] = b.x; r2[6] = b.y; r2[7] = b.z; r2[8] = b.w;
        r2[0] = (xs > 0)            ? row[xs - 1]     : 0.0f;
        r2[9] = (xs + MP_TX < MP_W) ? row[xs + MP_TX] : 0.0f;
    } else {
        #pragma unroll
        for (int i = 0; i < MP_TX + 2; i++) r2[i] = 0.0f;
    }

    // ---- vertical sort-3 per column, in place: r0=lo, r1=mid, r2=hi ----
    #pragma unroll
    for (int i = 0; i < MP_TX + 2; i++) {
        float a = r0[i], b = r1[i], c = r2[i];
        float mn = fminf(a, b);
        float mx = fmaxf(a, b);
        r0[i] = fminf(mn, c);                 // lo
        r2[i] = fmaxf(mx, c);                 // hi
        r1[i] = fmaxf(mn, fminf(mx, c));      // mid
    }

    // ---- horizontal combine: med3(max3(lo), med3(mid), min3(hi)) ----
    float o[MP_TX];
    #pragma unroll
    for (int i = 0; i < MP_TX; i++) {
        float mxlo = fmaxf(fmaxf(r0[i], r0[i + 1]), r0[i + 2]);
        float mnhi = fminf(fminf(r2[i], r2[i + 1]), r2[i + 2]);
        float mdmi = med3f(r1[i], r1[i + 1], r1[i + 2]);
        o[i] = med3f(mxlo, mdmi, mnhi);
    }

    float* orow = out + (size_t)bc * (MP_H * MP_W) + y * MP_W + xs;
    float4 o0 = make_float4(o[0], o[1], o[2], o[3]);
    float4 o1 = make_float4(o[4], o[5], o[6], o[7]);
    *(float4*)(orow)     = o0;
    *(float4*)(orow + 4) = o1;
}

extern "C" void kernel_launch(void* const* d_in, const int* in_sizes, int n_in,
                              void* d_out, int out_size) {
    (void)in_sizes; (void)n_in; (void)out_size;
    const float* x = (const float*)d_in[0];
    float* out = (float*)d_out;
    const int total_threads = MP_BC * MP_H * MP_SEGS;  // 1,572,864
    median3x3_kernel<<<total_threads / 256, 256>>>(x, out);
}

// round 4
// speedup vs baseline: 1.4247x; 1.4247x over previous
#include <cuda_runtime.h>
#include <cuda_bf16.h>

// MedianPool2d 3x3, zero padding, x: [16, 3, 512, 512] fp32.
// v2: vertical rolling window (8 output rows/thread) + shuffle halos.
// Exact median-of-9: per column sort3 (lo,mid,hi) via rolling pairwise
// min/max reuse, then med3(max3(lo), med3(mid), min3(hi)).

#define MP_W 512
#define MP_H 512
#define MP_BC 48           // 16 * 3
#define MP_TX 8            // pixels per thread (horizontal)
#define MP_TY 8            // output rows per thread (vertical)
#define MP_SEGS 64         // MP_W / MP_TX
#define MP_BANDS 64        // MP_H / MP_TY

__device__ __forceinline__ float med3f(float a, float b, float c) {
    return fmaxf(fminf(a, b), fminf(fmaxf(a, b), c));
}

// Load one image row segment [xs-1, xs+8] into r[0..9].
// Interior halos come from neighbor lanes via shuffle; only lane 0 / lane 31
// (warp-edge segments) fall back to a scalar LDG (or zero at image edge).
__device__ __forceinline__ void mp_load_row(const float* __restrict__ row,
                                            int xs, int lane, float r[10]) {
    float4 a = *(const float4*)(row + xs);
    float4 b = *(const float4*)(row + xs + 4);
    r[1] = a.x; r[2] = a.y; r[3] = a.z; r[4] = a.w;
    r[5] = b.x; r[6] = b.y; r[7] = b.z; r[8] = b.w;
    float left  = __shfl_up_sync(0xffffffffu, b.w, 1);   // prev seg's r[8]
    float right = __shfl_down_sync(0xffffffffu, a.x, 1); // next seg's r[1]
    if (lane == 0)  left  = (xs > 0)             ? __ldg(row + xs - 1)     : 0.0f;
    if (lane == 31) right = (xs + MP_TX < MP_W)  ? __ldg(row + xs + MP_TX) : 0.0f;
    r[0] = left; r[9] = right;
}

__global__ __launch_bounds__(256)
void median3x3_v2(const float* __restrict__ in, float* __restrict__ out) {
    const int gid  = blockIdx.x * 256 + threadIdx.x;
    const int lane = threadIdx.x & 31;
    const int seg  = gid & (MP_SEGS - 1);          // bits [0,6)
    const int yb   = (gid >> 6) & (MP_BANDS - 1);  // bits [6,12)
    const int bc   = gid >> 12;                    // bits [12,...)
    const int xs   = seg * MP_TX;
    const int y0   = yb * MP_TY;

    const float* base  = in  + (size_t)bc * (MP_H * MP_W);
    float*       obase = out + (size_t)bc * (MP_H * MP_W);

    // Rolling state: B = most recent raw row, pm/px = pairwise min/max of the
    // two most recent raw rows (the shared pair between consecutive windows).
    float B[10], C[10], pm[10], px[10];

    if (y0 > 0) {
        float A[10];
        mp_load_row(base + (y0 - 1) * MP_W, xs, lane, A);
        mp_load_row(base + y0 * MP_W, xs, lane, B);
        #pragma unroll
        for (int i = 0; i < 10; i++) {
            pm[i] = fminf(A[i], B[i]);
            px[i] = fmaxf(A[i], B[i]);
        }
    } else {
        // top band: row y0-1 is the zero pad
        mp_load_row(base + y0 * MP_W, xs, lane, B);
        #pragma unroll
        for (int i = 0; i < 10; i++) {
            pm[i] = fminf(0.0f, B[i]);
            px[i] = fmaxf(0.0f, B[i]);
        }
    }

    #pragma unroll
    for (int r = 0; r < MP_TY; r++) {
        const int yn = y0 + r + 1;
        if (yn < MP_H) {
            mp_load_row(base + yn * MP_W, xs, lane, C);
        } else {
            #pragma unroll
            for (int i = 0; i < 10; i++) C[i] = 0.0f;
        }

        // sort3 of (prev2, prev1, C) via shared pair (pm, px), third = C:
        //   lo = min(pm, C); hi = max(px, C); mid = max(pm, min(px, C))
        // then advance pair to (B=prev1, C).
        float lo[10], mid[10], hi[10];
        #pragma unroll
        for (int i = 0; i < 10; i++) {
            float t = fminf(px[i], C[i]);
            lo[i]  = fminf(pm[i], C[i]);
            hi[i]  = fmaxf(px[i], C[i]);
            mid[i] = fmaxf(pm[i], t);
            pm[i]  = fminf(B[i], C[i]);
            px[i]  = fmaxf(B[i], C[i]);
            B[i]   = C[i];
        }

        float o[MP_TX];
        #pragma unroll
        for (int i = 0; i < MP_TX; i++) {
            float mxlo = fmaxf(fmaxf(lo[i], lo[i + 1]), lo[i + 2]);
            float mnhi = fminf(fminf(hi[i], hi[i + 1]), hi[i + 2]);
            float mdmi = med3f(mid[i], mid[i + 1], mid[i + 2]);
            o[i] = med3f(mxlo, mdmi, mnhi);
        }

        float* orow = obase + (size_t)(y0 + r) * MP_W + xs;
        *(float4*)(orow)     = make_float4(o[0], o[1], o[2], o[3]);
        *(float4*)(orow + 4) = make_float4(o[4], o[5], o[6], o[7]);
    }
}

extern "C" void kernel_launch(void* const* d_in, const int* in_sizes, int n_in,
                              void* d_out, int out_size) {
    (void)in_sizes; (void)n_in; (void)out_size;
    const float* x = (const float*)d_in[0];
    float* out = (float*)d_out;
    const int total_threads = MP_BC * MP_BANDS * MP_SEGS;  // 196,608
    median3x3_v2<<<total_threads / 256, 256>>>(x, out);
}